// round 11
// baseline (speedup 1.0000x reference)
#include <cuda_runtime.h>
#include <cuda_bf16.h>

// PointMatcher: pred (N=1024,20,2) vs gt (M=2048,20,2)
// dist(i,j) = mean_p ||pred[i,p]-gt[j,p]|| ; argmin over j per i.
// Quad-split-P: 4 threads (butterfly lane^4, lane^8) each own 5 of 20 points
// (strided p = pq+4k) and 4 gt rows per tile. 1024-thread blocks @ 32 regs
// -> 2 CTAs/SM -> ~2x resident warps vs 512-thread/64-reg version.
// Tiles filled by cp.async.bulk + mbarrier, double-buffered.
// Outputs concatenated in d_out (float32):
//   [0..N*40) matched gt rows | [N*40..N*41) confidence | [N*41..N*42) indices

#define BI      4       // pred rows per block
#define TJ      256     // gt rows per tile
#define P       20
#define PH      5       // points per thread (quarter of P)
#define ROWF    40      // floats per row; raw stride (contiguous tile for TMA)
#define THREADS 1024
#define TILEF   (TJ * ROWF)                 // 10240 floats
#define TILEB   (TILEF * 4)                 // 40960 bytes
#define SMEM_BYTES (2*TILEB + BI*8 + 2*8)

typedef unsigned long long ull;

__device__ __forceinline__ float fsqrt_approx(float x) {
    float r;
    asm("sqrt.approx.f32 %0, %1;" : "=f"(r) : "f"(x));
    return r;
}
// sqrt((gx-px)^2+(gy-py)^2), pneg = packed {-px,-py}
__device__ __forceinline__ float pd(ull g, ull pneg) {
    ull d, q;
    asm("add.rn.f32x2 %0, %1, %2;" : "=l"(d) : "l"(g), "l"(pneg));
    asm("mul.rn.f32x2 %0, %1, %2;" : "=l"(q) : "l"(d), "l"(d));
    float a, b;
    asm("mov.b64 {%0,%1}, %2;" : "=f"(a), "=f"(b) : "l"(q));
    return fsqrt_approx(a + b);
}
__device__ __forceinline__ void mbar_init(unsigned mbar, unsigned cnt) {
    asm volatile("mbarrier.init.shared.b64 [%0], %1;" :: "r"(mbar), "r"(cnt) : "memory");
}
__device__ __forceinline__ void mbar_expect_tx(unsigned mbar, unsigned bytes) {
    asm volatile("mbarrier.arrive.expect_tx.shared.b64 _, [%0], %1;"
                 :: "r"(mbar), "r"(bytes) : "memory");
}
__device__ __forceinline__ void bulk_ld(unsigned dst, const void* src,
                                        unsigned bytes, unsigned mbar) {
    asm volatile(
        "cp.async.bulk.shared::cluster.global.mbarrier::complete_tx::bytes "
        "[%0], [%1], %2, [%3];"
        :: "r"(dst), "l"(src), "r"(bytes), "r"(mbar) : "memory");
}
__device__ __forceinline__ void mbar_wait(unsigned mbar, unsigned phase) {
    asm volatile(
        "{\n\t.reg .pred P1;\n\t"
        "W_%=:\n\t"
        "mbarrier.try_wait.parity.acquire.cta.shared::cta.b64 P1, [%0], %1, 0x989680;\n\t"
        "@P1 bra D_%=;\n\t"
        "bra W_%=;\n\t"
        "D_%=:\n\t}"
        :: "r"(mbar), "r"(phase) : "memory");
}

__global__ __launch_bounds__(THREADS, 2)
void pointmatcher_kernel(const float* __restrict__ pred,
                         const float* __restrict__ gt,
                         float* __restrict__ out_mp,
                         float* __restrict__ out_conf,
                         float* __restrict__ out_idx,
                         int N, int M)
{
    extern __shared__ __align__(16) float smem[];
    float* buf0 = smem;
    float* buf1 = smem + TILEF;
    ull*   best = (ull*)(smem + 2 * TILEF);
    unsigned mbar0 = (unsigned)__cvta_generic_to_shared(best + BI);
    unsigned mbar1 = mbar0 + 8;

    const int tid = threadIdx.x;
    const int il  = tid & 3;             // pred row within block
    const int pq  = (tid >> 2) & 3;      // point quarter (partners lane^4, ^8)
    const int jl  = tid >> 4;            // 0..63 -> rows jl+{0,64,128,192}
    const int i   = blockIdx.x * BI + il;

    if (tid < BI) best[tid] = ~0ull;
    if (tid == 0) { mbar_init(mbar0, 1); mbar_init(mbar1, 1); }

    // 5 pred points (indices pq+4k), negated, packed {-x,-y}. 10 regs.
    ull pr[PH];
    {
        const float2* p2 = (const float2*)(pred + (size_t)i * ROWF);
        #pragma unroll
        for (int k = 0; k < PH; k++) {
            float2 v = p2[pq + 4 * k];
            float nx = -v.x, ny = -v.y;
            asm("mov.b64 %0, {%1,%2};" : "=l"(pr[k]) : "f"(nx), "f"(ny));
        }
    }

    __syncthreads();                     // mbarrier init + best[] visible
    if (tid == 0) {                      // prefetch tile 0: ONE bulk copy
        mbar_expect_tx(mbar0, TILEB);
        bulk_ld((unsigned)__cvta_generic_to_shared(buf0), gt, TILEB, mbar0);
    }

    float minv = 3.402823466e+38f;       // min of SUM over P (mean deferred)
    int   minj = 0;
    const int ntiles = M / TJ;           // 8

    for (int t = 0; t < ntiles; t++) {
        unsigned mb = (t & 1) ? mbar1 : mbar0;
        mbar_wait(mb, (t >> 1) & 1);     // tile t landed
        __syncthreads();                 // all threads done with other buf

        if (tid == 0 && t + 1 < ntiles) {
            unsigned mbn = ((t + 1) & 1) ? mbar1 : mbar0;
            float* dst = ((t + 1) & 1) ? buf1 : buf0;
            mbar_expect_tx(mbn, TILEB);
            bulk_ld((unsigned)__cvta_generic_to_shared(dst),
                    gt + (size_t)(t + 1) * TILEF, TILEB, mbn);
        }

        // Base: row jl, point pq (8B-aligned LDS.64, conflict-free banks).
        const float* tb = (t & 1) ? buf1 : buf0;
        const ull* bp = (const ull*)(tb + jl * ROWF) + pq;
        float s0 = 0.f, s1 = 0.f, s2 = 0.f, s3 = 0.f;
        #pragma unroll
        for (int k = 0; k < PH; k++) {   // point index pq+4k -> ull offset 4k
            ull g0 = bp[4 * k];
            ull g1 = bp[4 * k +  64 * (ROWF / 2)];
            ull g2 = bp[4 * k + 128 * (ROWF / 2)];
            ull g3 = bp[4 * k + 192 * (ROWF / 2)];
            ull pk = pr[k];
            s0 += pd(g0, pk);
            s1 += pd(g1, pk);
            s2 += pd(g2, pk);
            s3 += pd(g3, pk);
        }
        // Butterfly-combine the 4 point-quarters (same il, jl).
        s0 += __shfl_xor_sync(0xffffffffu, s0, 4);
        s0 += __shfl_xor_sync(0xffffffffu, s0, 8);
        s1 += __shfl_xor_sync(0xffffffffu, s1, 4);
        s1 += __shfl_xor_sync(0xffffffffu, s1, 8);
        s2 += __shfl_xor_sync(0xffffffffu, s2, 4);
        s2 += __shfl_xor_sync(0xffffffffu, s2, 8);
        s3 += __shfl_xor_sync(0xffffffffu, s3, 4);
        s3 += __shfl_xor_sync(0xffffffffu, s3, 8);

        int jb = t * TJ + jl;
        if (s0 < minv) { minv = s0; minj = jb;       }  // ascending j order:
        if (s1 < minv) { minv = s1; minj = jb + 64;  }  // strict '<' keeps
        if (s2 < minv) { minv = s2; minj = jb + 128; }  // first occurrence
        if (s3 < minv) { minv = s3; minj = jb + 192; }
    }

    // Block argmin: packed (dist_bits, j); min == (min dist, then min j).
    // Only pq==0 issues (all quarters hold identical totals after shfl).
    if (pq == 0) {
        ull key = ((ull)__float_as_uint(minv) << 32) | (unsigned)minj;
        atomicMin(&best[il], key);
    }
    __syncthreads();

    if (tid < BI) {
        ull b = best[tid];
        int j = (int)(unsigned)b;
        float md = __uint_as_float((unsigned)(b >> 32)) * (1.0f / (float)P);
        int row  = blockIdx.x * BI + tid;
        out_conf[row] = (md > 2.0f) ? 0.0f : expf(-md);
        out_idx[row]  = (float)j;
    }
    if (tid < BI * ROWF) {
        int ilg = tid / ROWF;
        int k   = tid - ilg * ROWF;
        int j   = (int)(unsigned)best[ilg];
        out_mp[(blockIdx.x * BI + ilg) * ROWF + k] = gt[(size_t)j * ROWF + k];
    }
}

extern "C" void kernel_launch(void* const* d_in, const int* in_sizes, int n_in,
                              void* d_out, int out_size)
{
    const float* pred = (const float*)d_in[0];
    const float* gt   = (const float*)d_in[1];
    float* out        = (float*)d_out;

    int N = in_sizes[0] / ROWF;   // 1024
    int M = in_sizes[1] / ROWF;   // 2048

    float* out_mp   = out;
    float* out_conf = out + (size_t)N * ROWF;
    float* out_idx  = out + (size_t)N * ROWF + N;

    static bool attr_set = false;  // host-side only; not in the captured graph
    if (!attr_set) {
        cudaFuncSetAttribute(pointmatcher_kernel,
                             cudaFuncAttributeMaxDynamicSharedMemorySize,
                             SMEM_BYTES);
        attr_set = true;
    }

    pointmatcher_kernel<<<N / BI, THREADS, SMEM_BYTES>>>(
        pred, gt, out_mp, out_conf, out_idx, N, M);
}